// round 16
// baseline (speedup 1.0000x reference)
#include <cuda_runtime.h>
#include <cuda_fp16.h>
#include <cstdint>
#include <math.h>

#define Bk 16
#define Sk 512
#define Dk 512
#define Hh 4
#define DKk 128
#define FFk 1024
#define Lk 4
#define QKVN 4608              // 3 branches x (q|k|v) x 512

typedef __half  f16;
typedef __half2 f162;

// ==================== scratch (device globals; no allocation) ===============
__device__ float g_h  [Bk*Sk*Dk];
__device__ float g_o2 [Bk*Sk*(Dk/2)];
__device__ f16 g_h2  [Bk*Sk*Dk];
__device__ f16 g_qkvh[(size_t)Bk*Sk*QKVN];
__device__ f16 g_ctx [(size_t)Bk*Sk*1536];
__device__ f16 g_f   [Bk*Sk*FFk];
__device__ f16 g_mbias[(size_t)3*Bk*Sk*Sk];      // additive mask bias (0 / -1e4)
// weights (fp16)
__device__ f16 g_qkvwh[(size_t)Lk*Dk*QKVN];
__device__ float g_qkvb[(size_t)Lk*QKVN];
__device__ f16 g_wouth[(size_t)Lk*1536*Dk];
__device__ float g_woutb[(size_t)Lk*Dk];
__device__ f16 g_f1h[(size_t)Lk*Dk*FFk];
__device__ f16 g_f2h[(size_t)Lk*FFk*Dk];
__device__ f16 g_o1wh[Dk*Dk];
__device__ f16 g_o2wh[Dk*(Dk/2)];

// ==================== low-level helpers =====================================
__device__ __forceinline__ uint32_t smem_u32(const void* p) {
    return (uint32_t)__cvta_generic_to_shared(p);
}
__device__ __forceinline__ void ldsm4(uint32_t* r, uint32_t addr) {
    asm volatile("ldmatrix.sync.aligned.m8n8.x4.shared.b16 {%0,%1,%2,%3}, [%4];"
        : "=r"(r[0]), "=r"(r[1]), "=r"(r[2]), "=r"(r[3]) : "r"(addr));
}
__device__ __forceinline__ void ldsm4t(uint32_t* r, uint32_t addr) {
    asm volatile("ldmatrix.sync.aligned.m8n8.x4.trans.shared.b16 {%0,%1,%2,%3}, [%4];"
        : "=r"(r[0]), "=r"(r[1]), "=r"(r[2]), "=r"(r[3]) : "r"(addr));
}
__device__ __forceinline__ void mma_f16(float* c, const uint32_t* a,
                                        uint32_t b0, uint32_t b1) {
    asm volatile("mma.sync.aligned.m16n8k16.row.col.f32.f16.f16.f32 "
        "{%0,%1,%2,%3},{%4,%5,%6,%7},{%8,%9},{%0,%1,%2,%3};"
        : "+f"(c[0]), "+f"(c[1]), "+f"(c[2]), "+f"(c[3])
        : "r"(a[0]), "r"(a[1]), "r"(a[2]), "r"(a[3]), "r"(b0), "r"(b1));
}
__device__ __forceinline__ void cp16(uint32_t saddr, const f16* g) {
    asm volatile("cp.async.cg.shared.global [%0], [%1], 16;"
        :: "r"(saddr), "l"(__cvta_generic_to_global(g)) : "memory");
}
#define CP_COMMIT()   asm volatile("cp.async.commit_group;" ::: "memory")
#define CP_WAIT(n)    asm volatile("cp.async.wait_group %0;" :: "n"(n) : "memory")

__device__ __forceinline__ void hstore2(f16* p, size_t off, float x, float y) {
    *(f162*)(p + off) = __halves2half2(__float2half_rn(x), __float2half_rn(y));
}
__device__ __forceinline__ uint32_t pack_h2(float x, float y) {
    f162 h = __halves2half2(__float2half_rn(x), __float2half_rn(y));
    return *(uint32_t*)&h;
}

// ==================== smem tile loaders =====================================
// A-style: 128 rows x 32 f16, pitch 80B  (256-thread version, used by flash)
#define TA_BYTES 10240
__device__ __forceinline__ void cpA(uint32_t sbase, const f16* g, int ld, int tid) {
    #pragma unroll
    for (int i = 0; i < 2; i++) {
        int idx = tid + i * 256;
        int r = idx >> 2, c = idx & 3;
        cp16(sbase + (uint32_t)(r * 80 + c * 16), g + (size_t)r * ld + c * 8);
    }
}
// A-style 64 rows x 32 f16 (one cp16 per thread, 256 threads)
__device__ __forceinline__ void cpA64(uint32_t sbase, const f16* g, int ld, int tid) {
    int r = tid >> 2, c = tid & 3;
    cp16(sbase + (uint32_t)(r * 80 + c * 16), g + (size_t)r * ld + c * 8);
}
// B NN-style: 32 rows (k) x 128 cols (n), pitch 256B, XOR swizzle (256 thr)
#define TB_BYTES 8192
__device__ __forceinline__ void cpB_nn(uint32_t sbase, const f16* g, int ld, int tid) {
    #pragma unroll
    for (int i = 0; i < 2; i++) {
        int idx = tid + i * 256;
        int k = idx >> 4, c = idx & 15;
        cp16(sbase + (uint32_t)(k * 256 + ((c ^ (k & 7)) << 4)),
             g + (size_t)k * ld + c * 8);
    }
}
// ---- 128-thread loaders (wgemm) ----
__device__ __forceinline__ void cpA_128(uint32_t sbase, const f16* g, int ld, int tid) {
    #pragma unroll
    for (int i = 0; i < 4; i++) {
        int idx = tid + i * 128;
        int r = idx >> 2, c = idx & 3;
        cp16(sbase + (uint32_t)(r * 80 + c * 16), g + (size_t)r * ld + c * 8);
    }
}
__device__ __forceinline__ void cpB_nn_128(uint32_t sbase, const f16* g, int ld, int tid) {
    #pragma unroll
    for (int i = 0; i < 4; i++) {
        int idx = tid + i * 128;
        int k = idx >> 4, c = idx & 15;
        cp16(sbase + (uint32_t)(k * 256 + ((c ^ (k & 7)) << 4)),
             g + (size_t)k * ld + c * 8);
    }
}

// ==================== wgemm v3: 64x64 warp tiles, K64 stages, 3-deep ========
// stage: A0 10240 | A1 10240 | B0 8192 | B1 8192 = 36864
#define STK64   36864
#define SM_K64  (3 * STK64)     // 110592
template<bool RELU, bool ACCUM, bool F16OUT>
__global__ void __launch_bounds__(128, 2)
wgemm_kernel(const f16* __restrict__ Ah, const f16* __restrict__ Bh,
             const float* __restrict__ bias,
             float* __restrict__ C, f16* __restrict__ Ch,
             int M, int N, int K)
{
    extern __shared__ __align__(128) char smem[];
    const uint32_t sb = smem_u32(smem);
    const int tid = threadIdx.x, lane = tid & 31, w = tid >> 5;  // w: 0..3
    const int wm = (w & 1) * 64, wn = (w >> 1) * 64;
    const int bm = blockIdx.y * 128, bn = blockIdx.x * 128;
    const int NC = K >> 6;                  // K64 stages

    float acc[4][8][4];
    #pragma unroll
    for (int i = 0; i < 4; i++)
        #pragma unroll
        for (int j = 0; j < 8; j++)
            #pragma unroll
            for (int q = 0; q < 4; q++) acc[i][j][q] = 0.f;

    const f16* Ag = Ah + (size_t)bm * K;
    const f16* Bg = Bh + bn;

    auto load = [&](int c, int stg) {
        uint32_t s0 = sb + stg * STK64;
        cpA_128   (s0,             Ag + c * 64,      K, tid);
        cpA_128   (s0 + 10240,     Ag + c * 64 + 32, K, tid);
        cpB_nn_128(s0 + 20480,     Bg + (size_t)(c * 64)      * N, N, tid);
        cpB_nn_128(s0 + 28672,     Bg + (size_t)(c * 64 + 32) * N, N, tid);
        CP_COMMIT();
    };

    load(0, 0);
    load(1, 1);
    int stg = 0;
    for (int c = 0; c < NC; c++) {
        if (c + 1 < NC) { CP_WAIT(1); } else { CP_WAIT(0); }
        __syncthreads();
        // load(c+2) targets the stage consumed at c-1; every warp has passed
        // this iteration's barrier (after its c-1 compute) => no hazard.
        if (c + 2 < NC) load(c + 2, (stg + 2 > 2) ? stg - 1 : stg + 2);
        #pragma unroll
        for (int sub = 0; sub < 2; sub++) {
            uint32_t aH = sb + stg * STK64 + sub * 10240;
            uint32_t bH = sb + stg * STK64 + 20480 + sub * 8192;
            #pragma unroll
            for (int s = 0; s < 2; s++) {
                uint32_t ah[4][4], bh[4][4];
                uint32_t abase = aH + (uint32_t)((wm + (lane & 15)) * 80
                               + (s * 2 + (lane >> 4)) * 16);
                #pragma unroll
                for (int mt = 0; mt < 4; mt++)
                    ldsm4(ah[mt], abase + (uint32_t)(mt * 16 * 80));
                int k  = s * 16 + (lane & 7) + ((lane >> 3) & 1) * 8;
                int cb = (wn >> 3) + (lane >> 4);
                uint32_t ro = bH + (uint32_t)(k * 256);
                #pragma unroll
                for (int t = 0; t < 4; t++) {
                    uint32_t off = ro + (uint32_t)(((cb + t * 2) ^ (k & 7)) << 4);
                    ldsm4t(bh[t], off);
                }
                #pragma unroll
                for (int mt = 0; mt < 4; mt++)
                    #pragma unroll
                    for (int j = 0; j < 8; j++) {
                        int t = j >> 1, o = j & 1;
                        mma_f16(acc[mt][j], ah[mt], bh[t][o * 2], bh[t][o * 2 + 1]);
                    }
            }
        }
        stg = (stg == 2) ? 0 : stg + 1;
    }

    #pragma unroll
    for (int mt = 0; mt < 4; mt++) {
        int r0 = bm + wm + mt * 16 + (lane >> 2);
        #pragma unroll
        for (int j = 0; j < 8; j++) {
            int col = bn + wn + j * 8 + (lane & 3) * 2;
            float b0 = bias[col], b1 = bias[col + 1];
            float v00 = acc[mt][j][0] + b0, v01 = acc[mt][j][1] + b1;
            float v10 = acc[mt][j][2] + b0, v11 = acc[mt][j][3] + b1;
            size_t o0 = (size_t)r0 * N + col;
            size_t o1 = (size_t)(r0 + 8) * N + col;
            if (ACCUM) {
                float2 c0 = *(const float2*)(C + o0);
                float2 c1 = *(const float2*)(C + o1);
                v00 += c0.x; v01 += c0.y; v10 += c1.x; v11 += c1.y;
            }
            if (RELU) {
                v00 = fmaxf(v00, 0.f); v01 = fmaxf(v01, 0.f);
                v10 = fmaxf(v10, 0.f); v11 = fmaxf(v11, 0.f);
            }
            if (F16OUT) {
                hstore2(Ch, o0, v00, v01);
                hstore2(Ch, o1, v10, v11);
            } else {
                float2 r; r.x = v00; r.y = v01; *(float2*)(C + o0) = r;
                float2 s; s.x = v10; s.y = v11; *(float2*)(C + o1) = s;
            }
        }
    }
}

// ==================== flash attention v5 (pure fp16) ========================
// 256 threads; warp w owns q-rows w*16..w*16+15 of a 128-row Q tile.
// K iterated in 8 tiles of 64 rows; 2 CTAs/SM.
// smem: Q 4x10240 | K 2x20480 | V 2x8192 = 98304
#define F3_QB 0
#define F3_KS 20480
#define F3_KB 40960
#define F3_VS 8192
#define F3_VB (F3_KB + 2 * F3_KS)      // 81920
#define F3_SM (F3_VB + 2 * F3_VS)      // 98304

__global__ void __launch_bounds__(256, 2)
flash_kernel(const f16* __restrict__ qkvh, const f16* __restrict__ mbias,
             f16* __restrict__ ctx)
{
    extern __shared__ __align__(128) char smem[];
    const uint32_t sb = smem_u32(smem);
    const int tid = threadIdx.x, lane = tid & 31, w = tid >> 5;
    const int wm = w * 16;
    const int qt = blockIdx.x, bh = blockIdx.y, brn = blockIdx.z;
    const int b = bh >> 2, h = bh & 3;
    const size_t rowbase = (size_t)b * Sk;
    const f16* Qh = qkvh + (rowbase + qt * 128) * QKVN + brn * 1536 + h * DKk;
    const f16* Kh = qkvh + rowbase * QKVN + brn * 1536 + 512 + h * DKk;
    const f16* Vh = qkvh + rowbase * QKVN + brn * 1536 + 1024 + h * DKk;
    const f16* mp = mbias + ((size_t)brn * Bk + b) * Sk * Sk;

    auto loadK_body = [&](int kt, int stg2) {
        #pragma unroll
        for (int kc = 0; kc < 4; kc++)
            cpA64(sb + F3_KB + stg2 * F3_KS + kc * 5120,
                  Kh + (size_t)(kt * 64) * QKVN + kc * 32, QKVN, tid);
    };
    auto loadV = [&](int kt, int c, int stg2) {
        cpB_nn(sb + F3_VB + stg2 * F3_VS,
               Vh + (size_t)(kt * 64 + c * 32) * QKVN, QKVN, tid);
        CP_COMMIT();
    };

    // group 0: Q (resident) + K tile 0
    #pragma unroll
    for (int c = 0; c < 4; c++)
        cpA(sb + F3_QB + c * 10240, Qh + c * 32, QKVN, tid);
    loadK_body(0, 0);
    CP_COMMIT();
    loadV(0, 0, 0);   // group 1
    loadV(0, 1, 1);   // group 2

    float m0 = -1e30f, m1 = -1e30f, l0 = 0.f, l1 = 0.f;
    float acc_o[16][4];
    #pragma unroll
    for (int j = 0; j < 16; j++)
        #pragma unroll
        for (int q = 0; q < 4; q++) acc_o[j][q] = 0.f;

    const float scale = 0.08838834764831845f;  // 1/sqrt(128)
    const int r0loc = qt * 128 + wm + (lane >> 2);

    for (int kt = 0; kt < 8; kt++) {
        CP_WAIT(2);
        __syncthreads();

        float acc_s[8][4];
        #pragma unroll
        for (int j = 0; j < 8; j++)
            #pragma unroll
            for (int q = 0; q < 4; q++) acc_s[j][q] = 0.f;

        // ---- S = Qh @ Kh^T over 4 dk-chunks (64 k-rows) ----
        #pragma unroll
        for (int kc = 0; kc < 4; kc++) {
            uint32_t QCH = sb + F3_QB + kc * 10240;
            uint32_t KC  = sb + F3_KB + (kt & 1) * F3_KS + kc * 5120;
            #pragma unroll
            for (int s = 0; s < 2; s++) {
                uint32_t ah[4];
                ldsm4(ah, QCH + (uint32_t)((wm + (lane & 15)) * 80
                          + (s * 2 + (lane >> 4)) * 16));
                uint32_t bh4[4][4];
                #pragma unroll
                for (int t = 0; t < 4; t++)
                    ldsm4(bh4[t], KC + (uint32_t)((t * 16 + (lane & 15)) * 80
                              + (s * 2 + (lane >> 4)) * 16));
                #pragma unroll
                for (int t = 0; t < 4; t++)
                    #pragma unroll
                    for (int o = 0; o < 2; o++)
                        mma_f16(acc_s[t * 2 + o], ah, bh4[t][o], bh4[t][o + 2]);
            }
        }
        if (kt < 7) { loadK_body(kt + 1, (kt + 1) & 1); CP_COMMIT(); }

        // ---- additive mask + scale + online softmax (64 cols) ----
        const f16* mrow0 = mp + (size_t)r0loc * Sk + kt * 64;
        const f16* mrow1 = mrow0 + 8 * Sk;
        float rmax0 = -1e30f, rmax1 = -1e30f;
        #pragma unroll
        for (int j = 0; j < 8; j++) {
            int col = j * 8 + (lane & 3) * 2;
            f162 q0 = *(const f162*)(mrow0 + col);
            f162 q1 = *(const f162*)(mrow1 + col);
            acc_s[j][0] = acc_s[j][0] * scale + __half2float(__low2half(q0));
            acc_s[j][1] = acc_s[j][1] * scale + __half2float(__high2half(q0));
            acc_s[j][2] = acc_s[j][2] * scale + __half2float(__low2half(q1));
            acc_s[j][3] = acc_s[j][3] * scale + __half2float(__high2half(q1));
            rmax0 = fmaxf(rmax0, fmaxf(acc_s[j][0], acc_s[j][1]));
            rmax1 = fmaxf(rmax1, fmaxf(acc_s[j][2], acc_s[j][3]));
        }
        rmax0 = fmaxf(rmax0, __shfl_xor_sync(0xffffffffu, rmax0, 1));
        rmax0 = fmaxf(rmax0, __shfl_xor_sync(0xffffffffu, rmax0, 2));
        rmax1 = fmaxf(rmax1, __shfl_xor_sync(0xffffffffu, rmax1, 1));
        rmax1 = fmaxf(rmax1, __shfl_xor_sync(0xffffffffu, rmax1, 2));
        float mn0 = fmaxf(m0, rmax0), mn1 = fmaxf(m1, rmax1);
        float f0 = __expf(m0 - mn0), f1 = __expf(m1 - mn1);
        float rs0 = 0.f, rs1 = 0.f;
        #pragma unroll
        for (int j = 0; j < 8; j++) {
            float p0 = __expf(acc_s[j][0] - mn0);
            float p1 = __expf(acc_s[j][1] - mn0);
            float p2 = __expf(acc_s[j][2] - mn1);
            float p3 = __expf(acc_s[j][3] - mn1);
            acc_s[j][0] = p0; acc_s[j][1] = p1;
            acc_s[j][2] = p2; acc_s[j][3] = p3;
            rs0 += p0 + p1; rs1 += p2 + p3;
        }
        rs0 += __shfl_xor_sync(0xffffffffu, rs0, 1);
        rs0 += __shfl_xor_sync(0xffffffffu, rs0, 2);
        rs1 += __shfl_xor_sync(0xffffffffu, rs1, 1);
        rs1 += __shfl_xor_sync(0xffffffffu, rs1, 2);
        l0 = l0 * f0 + rs0; l1 = l1 * f1 + rs1;
        m0 = mn0; m1 = mn1;
        #pragma unroll
        for (int j = 0; j < 16; j++) {
            acc_o[j][0] *= f0; acc_o[j][1] *= f0;
            acc_o[j][2] *= f1; acc_o[j][3] *= f1;
        }

        // ---- O += P @ V over 2 chunks of 32 k-rows (single-term) ----
        #pragma unroll
        for (int c = 0; c < 2; c++) {
            if (kt < 7)      { CP_WAIT(2); }
            else if (c == 0) { CP_WAIT(1); }
            else             { CP_WAIT(0); }
            __syncthreads();
            uint32_t VST = sb + F3_VB + c * F3_VS;
            #pragma unroll
            for (int s = 0; s < 2; s++) {
                int j0 = c * 4 + s * 2;
                uint32_t ph[4];
                ph[0] = pack_h2(acc_s[j0][0],     acc_s[j0][1]);
                ph[1] = pack_h2(acc_s[j0][2],     acc_s[j0][3]);
                ph[2] = pack_h2(acc_s[j0 + 1][0], acc_s[j0 + 1][1]);
                ph[3] = pack_h2(acc_s[j0 + 1][2], acc_s[j0 + 1][3]);
                int lk = s * 16 + (lane & 7) + ((lane >> 3) & 1) * 8;
                int cb = lane >> 4;
                uint32_t ro = VST + (uint32_t)(lk * 256);
                #pragma unroll
                for (int half = 0; half < 2; half++) {
                    uint32_t vh4[4][4];
                    #pragma unroll
                    for (int t = 0; t < 4; t++) {
                        int t2 = half * 4 + t;
                        uint32_t off = ro + (uint32_t)(((cb + t2 * 2) ^ (lk & 7)) << 4);
                        ldsm4t(vh4[t], off);
                    }
                    #pragma unroll
                    for (int t = 0; t < 4; t++)
                        #pragma unroll
                        for (int o = 0; o < 2; o++) {
                            int j = (half * 4 + t) * 2 + o;
                            mma_f16(acc_o[j], ph, vh4[t][o * 2], vh4[t][o * 2 + 1]);
                        }
                }
            }
            __syncthreads();
            if (kt < 7) loadV(kt + 1, c, c);
        }
    }

    // ---- epilogue: normalize + store ctx (fp16) ----
    float i0 = 1.f / l0, i1 = 1.f / l1;
    size_t gr0 = rowbase + (size_t)r0loc;
    int cc0 = brn * 512 + h * DKk;
    #pragma unroll
    for (int j = 0; j < 16; j++) {
        int col = cc0 + j * 8 + (lane & 3) * 2;
        hstore2(ctx, gr0 * 1536 + col, acc_o[j][0] * i0, acc_o[j][1] * i0);
        hstore2(ctx, (gr0 + 8) * 1536 + col, acc_o[j][2] * i1, acc_o[j][3] * i1);
    }
}

// ==================== weight prep (launch #1) ================================
__global__ void prep_w_kernel(const float* __restrict__ aw,
                              const float* __restrict__ ab,
                              const float* __restrict__ ff_w1,
                              const float* __restrict__ ff_w2,
                              const float* __restrict__ out1_w,
                              const float* __restrict__ out2_w,
                              f16* __restrict__ qkvwh, f16* __restrict__ wouth,
                              float* __restrict__ qkvb, float* __restrict__ woutb,
                              f16* __restrict__ f1h, f16* __restrict__ f2h,
                              f16* __restrict__ o1wh, f16* __restrict__ o2wh)
{
    int blk = blockIdx.x;
    if (blk < 18432) {
        size_t o = ((size_t)blk * 256 + threadIdx.x) * 2;
        size_t per = (size_t)Dk * QKVN;
        int l = (int)(o / per);
        size_t r = o % per;
        int k = (int)(r / QKVN);
        int c = (int)(r % QKVN);
        int brn = c / 1536, rem = c % 1536;
        int j = rem >> 9, n = rem & 511;
        const float* src = aw + ((((size_t)(l * 3 + brn) * 4 + j) * Dk + k) * Dk + n);
        float2 v = *(const float2*)src;
        hstore2(qkvwh, o, v.x, v.y);
    } else if (blk < 24576) {
        size_t o = ((size_t)(blk - 18432) * 256 + threadIdx.x) * 2;
        size_t per = (size_t)1536 * Dk;
        int l = (int)(o / per);
        size_t r = o % per;
        int k = (int)(r / Dk);
        int n = (int)(r % Dk);
        int brn = k / 512, kk = k % 512;
        const float* src = aw + ((((size_t)(l * 3 + brn) * 4 + 3) * Dk + kk) * Dk + n);
        float2 v = *(const float2*)src;
        hstore2(wouth, o, v.x, v.y);
    } else if (blk < 26624) {
        int i = ((blk - 24576) * 256 + threadIdx.x) * 4;
        float4 v = *(const float4*)(ff_w1 + i);
        hstore2(f1h, i, v.x, v.y);
        hstore2(f1h, i + 2, v.z, v.w);
    } else if (blk < 28672) {
        int i = ((blk - 26624) * 256 + threadIdx.x) * 4;
        float4 v = *(const float4*)(ff_w2 + i);
        hstore2(f2h, i, v.x, v.y);
        hstore2(f2h, i + 2, v.z, v.w);
    } else if (blk < 28928) {
        int i = ((blk - 28672) * 256 + threadIdx.x) * 4;
        float4 v = *(const float4*)(out1_w + i);
        hstore2(o1wh, i, v.x, v.y);
        hstore2(o1wh, i + 2, v.z, v.w);
    } else if (blk < 29056) {
        int i = ((blk - 28928) * 256 + threadIdx.x) * 4;
        float4 v = *(const float4*)(out2_w + i);
        hstore2(o2wh, i, v.x, v.y);
        hstore2(o2wh, i + 2, v.z, v.w);
    } else if (blk < 29128) {
        int o = (blk - 29056) * 256 + threadIdx.x;
        int l = o / QKVN, c = o % QKVN;
        int brn = c / 1536, rem = c % 1536;
        int j = rem >> 9, n = rem & 511;
        qkvb[o] = ab[((l * 3 + brn) * 4 + j) * Dk + n];
    } else {
        int o = (blk - 29128) * 256 + threadIdx.x;
        int l = o / Dk, n = o % Dk;
        float s = 0.f;
        for (int brn = 0; brn < 3; brn++)
            s += ab[((l * 3 + brn) * 4 + 3) * Dk + n];
        woutb[o] = s;
    }
}

// ==================== mask prep (launch #2) ==================================
__global__ void prep_mask_kernel(const int* __restrict__ dmask,
                                 const int* __restrict__ smask,
                                 const int* __restrict__ gmask,
                                 f16* __restrict__ mbias)
{
    size_t o = ((size_t)blockIdx.x * 256 + threadIdx.x) * 4;
    const size_t per = (size_t)Bk * Sk * Sk;
    int brn = (int)(o / per);
    size_t r = o % per;
    const int* src = (brn == 0) ? dmask : (brn == 1) ? smask : gmask;
    int4 m = *(const int4*)(src + r);
    f16* dst = mbias + o;
    dst[0] = __float2half_rn(m.x ? -1e4f : 0.f);
    dst[1] = __float2half_rn(m.y ? -1e4f : 0.f);
    dst[2] = __float2half_rn(m.z ? -1e4f : 0.f);
    dst[3] = __float2half_rn(m.w ? -1e4f : 0.f);
}

// ==================== reductions ============================================
__device__ __forceinline__ float warpReduceSum(float v) {
    #pragma unroll
    for (int o = 16; o > 0; o >>= 1) v += __shfl_xor_sync(0xffffffffu, v, o);
    return v;
}

// ==================== fused input projection + inorm (layer 0) ==============
__global__ void input_proj_inorm_kernel(const float* __restrict__ x,
                                        const float* __restrict__ cond,
                                        const float* __restrict__ in_w,
                                        const float* __restrict__ in_b,
                                        const float* __restrict__ cond_w,
                                        const float* __restrict__ cond_b,
                                        float* __restrict__ h,
                                        f16* __restrict__ y)
{
    __shared__ float xs[2][18];
    __shared__ float cs[2][89];
    __shared__ float s1[8], s2[8];
    int tok0 = blockIdx.x * 2;
    int t = threadIdx.x;          // 256
    if (t < 36)  xs[t / 18][t % 18] = x[(size_t)tok0 * 18 + t];
    if (t < 178) cs[t / 89][t % 89] = cond[(size_t)tok0 * 89 + t];
    __syncthreads();
    int half = t >> 7, lt = t & 127;
    int col = lt * 4;
    float4 ib = *(const float4*)(in_b + col);
    float4 cbv = *(const float4*)(cond_b + col);
    float a0 = ib.x + cbv.x, a1 = ib.y + cbv.y, a2 = ib.z + cbv.z, a3 = ib.w + cbv.w;
    #pragma unroll 3
    for (int k = 0; k < 18; k++) {
        float4 wv = *(const float4*)(in_w + k * Dk + col);
        float xv = xs[half][k];
        a0 = fmaf(xv, wv.x, a0); a1 = fmaf(xv, wv.y, a1);
        a2 = fmaf(xv, wv.z, a2); a3 = fmaf(xv, wv.w, a3);
    }
    #pragma unroll 3
    for (int k = 0; k < 89; k++) {
        float4 wv = *(const float4*)(cond_w + k * Dk + col);
        float cv = cs[half][k];
        a0 = fmaf(cv, wv.x, a0); a1 = fmaf(cv, wv.y, a1);
        a2 = fmaf(cv, wv.z, a2); a3 = fmaf(cv, wv.w, a3);
    }
    const size_t base = (size_t)(tok0 + half) * Dk;
    float4 r; r.x = a0; r.y = a1; r.z = a2; r.w = a3;
    *(float4*)(h + base + col) = r;
    float sum = warpReduceSum(a0 + a1 + a2 + a3);
    float sq  = warpReduceSum(a0*a0 + a1*a1 + a2*a2 + a3*a3);
    int wid = t >> 5;
    if ((t & 31) == 0) { s1[wid] = sum; s2[wid] = sq; }
    __syncthreads();
    int h4 = half * 4;
    float tot = s1[h4] + s1[h4+1] + s1[h4+2] + s1[h4+3];
    float tsq = s2[h4] + s2[h4+1] + s2[h4+2] + s2[h4+3];
    float mean = tot * (1.f / Dk);
    float var  = tsq * (1.f / Dk) - mean * mean;
    float rr = rsqrtf(var + 1e-5f);
    hstore2(y, base + col,     (a0 - mean) * rr, (a1 - mean) * rr);
    hstore2(y, base + col + 2, (a2 - mean) * rr, (a3 - mean) * rr);
}

// ==================== instance norm =========================================
__global__ void inorm_kernel(const float* __restrict__ x, f16* __restrict__ y)
{
    __shared__ float s1[8], s2[8];
    const size_t base = (size_t)blockIdx.x * Dk;
    int t = threadIdx.x;          // 256
    float a = x[base + t], b = x[base + t + 256];
    float sum = warpReduceSum(a + b);
    float sq  = warpReduceSum(a * a + b * b);
    if ((t & 31) == 0) { s1[t >> 5] = sum; s2[t >> 5] = sq; }
    __syncthreads();
    if (t < 32) {
        float v1 = (t < 8) ? s1[t] : 0.f;
        float v2 = (t < 8) ? s2[t] : 0.f;
        v1 = warpReduceSum(v1);
        v2 = warpReduceSum(v2);
        if (t == 0) { s1[0] = v1; s2[0] = v2; }
    }
    __syncthreads();
    float mean = s1[0] * (1.f / Dk);
    float var  = s2[0] * (1.f / Dk) - mean * mean;
    float r = rsqrtf(var + 1e-5f);
    y[base + t]       = __float2half_rn((a - mean) * r);
    y[base + t + 256] = __float2half_rn((b - mean) * r);
}

// ==================== split (for output head) ================================
__global__ void split_kernel(const float* __restrict__ x, f16* __restrict__ y)
{
    int i = (blockIdx.x * 256 + threadIdx.x) * 4;
    float4 v = *(const float4*)(x + i);
    hstore2(y, i,     v.x, v.y);
    hstore2(y, i + 2, v.z, v.w);
}

// ==================== final tiny head =======================================
__global__ void out3_kernel(const float* __restrict__ o2,
                            const float* __restrict__ w,
                            const float* __restrict__ b,
                            float* __restrict__ out)
{
    int idx = blockIdx.x * 256 + threadIdx.x;
    if (idx >= Bk * Sk * 2) return;
    int tok = idx >> 1, j = idx & 1;
    const float* o = o2 + (size_t)tok * 256;
    float acc = b[j];
    #pragma unroll 8
    for (int kk = 0; kk < 256; kk++) acc = fmaf(o[kk], w[kk * 2 + j], acc);
    out[idx] = acc;
}

// ============================ host launcher =================================
extern "C" void kernel_launch(void* const* d_in, const int* in_sizes, int n_in,
                              void* d_out, int out_size)
{
    const float* x      = (const float*)d_in[0];
    const float* cond   = (const float*)d_in[1];
    const int*   dmask  = (const int*)  d_in[2];
    const int*   smask  = (const int*)  d_in[3];
    const int*   gmask  = (const int*)  d_in[4];
    const float* attn_w = (const float*)d_in[5];
    const float* attn_b = (const float*)d_in[6];
    const float* ff_w1  = (const float*)d_in[7];
    const float* ff_b1  = (const float*)d_in[8];
    const float* ff_w2  = (const float*)d_in[9];
    const float* ff_b2  = (const float*)d_in[10];
    const float* in_w   = (const float*)d_in[11];
    const float* in_b   = (const float*)d_in[12];
    const float* cond_w = (const float*)d_in[13];
    const float* cond_b = (const float*)d_in[14];
    const float* out1_w = (const float*)d_in[15];
    const float* out1_b = (const float*)d_in[16];
    const float* out2_w = (const float*)d_in[17];
    const float* out2_b = (const float*)d_in[18];
    const float* out3_w = (const float*)d_in[19];
    const float* out3_b = (const float*)d_in[20];

    float *h, *o2, *qkvb, *woutb;
    f16 *h2, *qkvh, *ctx, *f, *mbias;
    f16 *qkvwh, *wouth, *f1h, *f2h, *o1wh, *o2wh;
    cudaGetSymbolAddress((void**)&h,      g_h);
    cudaGetSymbolAddress((void**)&o2,     g_o2);
    cudaGetSymbolAddress((void**)&qkvb,   g_qkvb);
    cudaGetSymbolAddress((void**)&woutb,  g_woutb);
    cudaGetSymbolAddress((void**)&h2,     g_h2);
    cudaGetSymbolAddress((void**)&qkvh,   g_qkvh);
    cudaGetSymbolAddress((void**)&ctx,    g_ctx);
    cudaGetSymbolAddress((void**)&f,      g_f);
    cudaGetSymbolAddress((void**)&mbias,  g_mbias);
    cudaGetSymbolAddress((void**)&qkvwh,  g_qkvwh);
    cudaGetSymbolAddress((void**)&wouth,  g_wouth);
    cudaGetSymbolAddress((void**)&f1h,    g_f1h);
    cudaGetSymbolAddress((void**)&f2h,    g_f2h);
    cudaGetSymbolAddress((void**)&o1wh,   g_o1wh);
    cudaGetSymbolAddress((void**)&o2wh,   g_o2wh);

    cudaFuncSetAttribute(wgemm_kernel<false,false,true>,
                         cudaFuncAttributeMaxDynamicSharedMemorySize, SM_K64);
    cudaFuncSetAttribute(wgemm_kernel<true,false,true>,
                         cudaFuncAttributeMaxDynamicSharedMemorySize, SM_K64);
    cudaFuncSetAttribute(wgemm_kernel<false,true,false>,
                         cudaFuncAttributeMaxDynamicSharedMemorySize, SM_K64);
    cudaFuncSetAttribute(wgemm_kernel<true,false,false>,
                         cudaFuncAttributeMaxDynamicSharedMemorySize, SM_K64);
    cudaFuncSetAttribute(flash_kernel,
                         cudaFuncAttributeMaxDynamicSharedMemorySize, F3_SM);

    const int M = Bk * Sk;           // 8192

    // #1: weight prep
    prep_w_kernel<<<29136, 256>>>(attn_w, attn_b, ff_w1, ff_w2, out1_w, out2_w,
                                  qkvwh, wouth, qkvb, woutb, f1h, f2h, o1wh, o2wh);
    // #2: mask prep
    prep_mask_kernel<<<12288, 256>>>(dmask, smask, gmask, mbias);

    // #3: input projection + layer-0 inorm fused
    input_proj_inorm_kernel<<<M / 2, 256>>>(x, cond, in_w, in_b, cond_w, cond_b,
                                            h, h2);

    for (int l = 0; l < Lk; l++) {
        if (l > 0) inorm_kernel<<<M, 256>>>(h, h2);
        // #4 (l=0): fused qkv — K64 stages, profiled slot
        wgemm_kernel<false,false,true><<<dim3(QKVN/128, 64), 128, SM_K64>>>(
            h2, qkvwh + (size_t)l * Dk * QKVN, qkvb + (size_t)l * QKVN,
            nullptr, qkvh, M, QKVN, Dk);
        flash_kernel<<<dim3(4, Bk*Hh, 3), 256, F3_SM>>>(qkvh, mbias, ctx);
        wgemm_kernel<false,true,false><<<dim3(4, 64), 128, SM_K64>>>(
            ctx, wouth + (size_t)l * 1536 * Dk, woutb + (size_t)l * Dk,
            h, nullptr, M, Dk, 1536);
        inorm_kernel<<<M, 256>>>(h, h2);
        wgemm_kernel<true,false,true><<<dim3(8, 64), 128, SM_K64>>>(
            h2, f1h + (size_t)l*Dk*FFk, ff_b1 + (size_t)l*FFk,
            nullptr, f, M, FFk, Dk);
        wgemm_kernel<false,true,false><<<dim3(4, 64), 128, SM_K64>>>(
            f, f2h + (size_t)l*FFk*Dk, ff_b2 + (size_t)l*Dk,
            h, nullptr, M, Dk, FFk);
    }

    // output head
    split_kernel<<<(M * Dk) / 1024, 256>>>(h, h2);
    wgemm_kernel<true,false,true><<<dim3(4, 64), 128, SM_K64>>>(
        h2, o1wh, out1_b, nullptr, ctx, M, Dk, Dk);
    wgemm_kernel<true,false,false><<<dim3(2, 64), 128, SM_K64>>>(
        ctx, o2wh, out2_b, o2, nullptr, M, Dk/2, Dk);
    out3_kernel<<<(M * 2 + 255) / 256, 256>>>(o2, out3_w, out3_b, (float*)d_out);
}

// round 17
// speedup vs baseline: 1.1427x; 1.1427x over previous
#include <cuda_runtime.h>
#include <cuda_fp16.h>
#include <cstdint>
#include <math.h>

#define Bk 16
#define Sk 512
#define Dk 512
#define Hh 4
#define DKk 128
#define FFk 1024
#define Lk 4
#define QKVN 4608              // 3 branches x (q|k|v) x 512

typedef __half  f16;
typedef __half2 f162;

// ==================== scratch (device globals; no allocation) ===============
__device__ float g_h  [Bk*Sk*Dk];
__device__ float g_o2 [Bk*Sk*(Dk/2)];
__device__ f16 g_h2  [Bk*Sk*Dk];
__device__ f16 g_qkvh[(size_t)Bk*Sk*QKVN];
__device__ f16 g_ctx [(size_t)Bk*Sk*1536];
__device__ f16 g_f   [Bk*Sk*FFk];
__device__ f16 g_mbias[(size_t)3*Bk*Sk*Sk];      // additive mask bias (0 / -1e4)
// weights (fp16)
__device__ f16 g_qkvwh[(size_t)Lk*Dk*QKVN];
__device__ float g_qkvb[(size_t)Lk*QKVN];
__device__ f16 g_wouth[(size_t)Lk*1536*Dk];
__device__ float g_woutb[(size_t)Lk*Dk];
__device__ f16 g_f1h[(size_t)Lk*Dk*FFk];
__device__ f16 g_f2h[(size_t)Lk*FFk*Dk];
__device__ f16 g_o1wh[Dk*Dk];
__device__ f16 g_o2wh[Dk*(Dk/2)];

// ==================== low-level helpers =====================================
__device__ __forceinline__ uint32_t smem_u32(const void* p) {
    return (uint32_t)__cvta_generic_to_shared(p);
}
__device__ __forceinline__ void ldsm4(uint32_t* r, uint32_t addr) {
    asm volatile("ldmatrix.sync.aligned.m8n8.x4.shared.b16 {%0,%1,%2,%3}, [%4];"
        : "=r"(r[0]), "=r"(r[1]), "=r"(r[2]), "=r"(r[3]) : "r"(addr));
}
__device__ __forceinline__ void ldsm4t(uint32_t* r, uint32_t addr) {
    asm volatile("ldmatrix.sync.aligned.m8n8.x4.trans.shared.b16 {%0,%1,%2,%3}, [%4];"
        : "=r"(r[0]), "=r"(r[1]), "=r"(r[2]), "=r"(r[3]) : "r"(addr));
}
__device__ __forceinline__ void mma_f16(float* c, const uint32_t* a,
                                        uint32_t b0, uint32_t b1) {
    asm volatile("mma.sync.aligned.m16n8k16.row.col.f32.f16.f16.f32 "
        "{%0,%1,%2,%3},{%4,%5,%6,%7},{%8,%9},{%0,%1,%2,%3};"
        : "+f"(c[0]), "+f"(c[1]), "+f"(c[2]), "+f"(c[3])
        : "r"(a[0]), "r"(a[1]), "r"(a[2]), "r"(a[3]), "r"(b0), "r"(b1));
}
__device__ __forceinline__ void cp16(uint32_t saddr, const f16* g) {
    asm volatile("cp.async.cg.shared.global [%0], [%1], 16;"
        :: "r"(saddr), "l"(__cvta_generic_to_global(g)) : "memory");
}
#define CP_COMMIT()   asm volatile("cp.async.commit_group;" ::: "memory")
#define CP_WAIT(n)    asm volatile("cp.async.wait_group %0;" :: "n"(n) : "memory")

__device__ __forceinline__ void hstore2(f16* p, size_t off, float x, float y) {
    *(f162*)(p + off) = __halves2half2(__float2half_rn(x), __float2half_rn(y));
}
__device__ __forceinline__ uint32_t pack_h2(float x, float y) {
    f162 h = __halves2half2(__float2half_rn(x), __float2half_rn(y));
    return *(uint32_t*)&h;
}

// ==================== smem tile loaders =====================================
// A-style: 128 rows x 32 f16, pitch 80B  (256-thread version, used by flash)
#define TA_BYTES 10240
__device__ __forceinline__ void cpA(uint32_t sbase, const f16* g, int ld, int tid) {
    #pragma unroll
    for (int i = 0; i < 2; i++) {
        int idx = tid + i * 256;
        int r = idx >> 2, c = idx & 3;
        cp16(sbase + (uint32_t)(r * 80 + c * 16), g + (size_t)r * ld + c * 8);
    }
}
// A-style 64 rows x 32 f16 (one cp16 per thread, 256 threads)
__device__ __forceinline__ void cpA64(uint32_t sbase, const f16* g, int ld, int tid) {
    int r = tid >> 2, c = tid & 3;
    cp16(sbase + (uint32_t)(r * 80 + c * 16), g + (size_t)r * ld + c * 8);
}
// B NN-style: 32 rows (k) x 128 cols (n), pitch 256B, XOR swizzle (256 thr)
#define TB_BYTES 8192
__device__ __forceinline__ void cpB_nn(uint32_t sbase, const f16* g, int ld, int tid) {
    #pragma unroll
    for (int i = 0; i < 2; i++) {
        int idx = tid + i * 256;
        int k = idx >> 4, c = idx & 15;
        cp16(sbase + (uint32_t)(k * 256 + ((c ^ (k & 7)) << 4)),
             g + (size_t)k * ld + c * 8);
    }
}
// ---- 128-thread loaders (wgemm) ----
__device__ __forceinline__ void cpA_128(uint32_t sbase, const f16* g, int ld, int tid) {
    #pragma unroll
    for (int i = 0; i < 4; i++) {
        int idx = tid + i * 128;
        int r = idx >> 2, c = idx & 3;
        cp16(sbase + (uint32_t)(r * 80 + c * 16), g + (size_t)r * ld + c * 8);
    }
}
__device__ __forceinline__ void cpB_nn_128(uint32_t sbase, const f16* g, int ld, int tid) {
    #pragma unroll
    for (int i = 0; i < 4; i++) {
        int idx = tid + i * 128;
        int k = idx >> 4, c = idx & 15;
        cp16(sbase + (uint32_t)(k * 256 + ((c ^ (k & 7)) << 4)),
             g + (size_t)k * ld + c * 8);
    }
}

// ==================== wgemm (R15 winner): 64x64 warp tiles, K32, 3-deep =====
#define ST_NN   18432           // A 10240 | B 8192
#define SM_NN3  (3 * ST_NN)     // 55296
template<bool RELU, bool ACCUM, bool F16OUT>
__global__ void __launch_bounds__(128, 2)
wgemm_kernel(const f16* __restrict__ Ah, const f16* __restrict__ Bh,
             const float* __restrict__ bias,
             float* __restrict__ C, f16* __restrict__ Ch,
             int M, int N, int K)
{
    extern __shared__ __align__(128) char smem[];
    const uint32_t sb = smem_u32(smem);
    const int tid = threadIdx.x, lane = tid & 31, w = tid >> 5;  // w: 0..3
    const int wm = (w & 1) * 64, wn = (w >> 1) * 64;
    const int bm = blockIdx.y * 128, bn = blockIdx.x * 128;
    const int NC = K >> 5;

    float acc[4][8][4];
    #pragma unroll
    for (int i = 0; i < 4; i++)
        #pragma unroll
        for (int j = 0; j < 8; j++)
            #pragma unroll
            for (int q = 0; q < 4; q++) acc[i][j][q] = 0.f;

    const f16* Ag = Ah + (size_t)bm * K;
    const f16* Bg = Bh + bn;

    auto load = [&](int c, int stg) {
        uint32_t s0 = sb + stg * ST_NN;
        cpA_128   (s0,            Ag + c * 32, K, tid);
        cpB_nn_128(s0 + TA_BYTES, Bg + (size_t)(c * 32) * N, N, tid);
        CP_COMMIT();
    };

    load(0, 0);
    load(1, 1);
    int stg = 0;
    for (int c = 0; c < NC; c++) {
        if (c + 1 < NC) { CP_WAIT(1); } else { CP_WAIT(0); }
        __syncthreads();
        if (c + 2 < NC) load(c + 2, (stg + 2 > 2) ? stg - 1 : stg + 2);
        uint32_t aH = sb + stg * ST_NN;
        uint32_t bH = aH + TA_BYTES;
        #pragma unroll
        for (int s = 0; s < 2; s++) {
            uint32_t ah[4][4], bh[4][4];
            uint32_t abase = aH + (uint32_t)((wm + (lane & 15)) * 80
                           + (s * 2 + (lane >> 4)) * 16);
            #pragma unroll
            for (int mt = 0; mt < 4; mt++)
                ldsm4(ah[mt], abase + (uint32_t)(mt * 16 * 80));
            int k  = s * 16 + (lane & 7) + ((lane >> 3) & 1) * 8;
            int cb = (wn >> 3) + (lane >> 4);
            uint32_t ro = bH + (uint32_t)(k * 256);
            #pragma unroll
            for (int t = 0; t < 4; t++) {
                uint32_t off = ro + (uint32_t)(((cb + t * 2) ^ (k & 7)) << 4);
                ldsm4t(bh[t], off);
            }
            #pragma unroll
            for (int mt = 0; mt < 4; mt++)
                #pragma unroll
                for (int j = 0; j < 8; j++) {
                    int t = j >> 1, o = j & 1;
                    mma_f16(acc[mt][j], ah[mt], bh[t][o * 2], bh[t][o * 2 + 1]);
                }
        }
        stg = (stg == 2) ? 0 : stg + 1;
    }

    #pragma unroll
    for (int mt = 0; mt < 4; mt++) {
        int r0 = bm + wm + mt * 16 + (lane >> 2);
        #pragma unroll
        for (int j = 0; j < 8; j++) {
            int col = bn + wn + j * 8 + (lane & 3) * 2;
            float b0 = bias[col], b1 = bias[col + 1];
            float v00 = acc[mt][j][0] + b0, v01 = acc[mt][j][1] + b1;
            float v10 = acc[mt][j][2] + b0, v11 = acc[mt][j][3] + b1;
            size_t o0 = (size_t)r0 * N + col;
            size_t o1 = (size_t)(r0 + 8) * N + col;
            if (ACCUM) {
                float2 c0 = *(const float2*)(C + o0);
                float2 c1 = *(const float2*)(C + o1);
                v00 += c0.x; v01 += c0.y; v10 += c1.x; v11 += c1.y;
            }
            if (RELU) {
                v00 = fmaxf(v00, 0.f); v01 = fmaxf(v01, 0.f);
                v10 = fmaxf(v10, 0.f); v11 = fmaxf(v11, 0.f);
            }
            if (F16OUT) {
                hstore2(Ch, o0, v00, v01);
                hstore2(Ch, o1, v10, v11);
            } else {
                float2 r; r.x = v00; r.y = v01; *(float2*)(C + o0) = r;
                float2 s; s.x = v10; s.y = v11; *(float2*)(C + o1) = s;
            }
        }
    }
}

// ==================== flash attention v6 (64-row V stages) ==================
// 256 threads; warp w owns q-rows w*16..w*16+15 of a 128-row Q tile.
// K in 8 tiles of 64 rows; V in 64-row stages (one per kt); 2 CTAs/SM.
// smem: Q 4x10240 | K 2x20480 | V 2x16384 = 114688  (x2 CTAs = 224 KB/SM)
#define F3_QB 0
#define F3_KS 20480
#define F3_KB 40960
#define F3_VS 16384
#define F3_VB (F3_KB + 2 * F3_KS)      // 81920
#define F3_SM (F3_VB + 2 * F3_VS)      // 114688

__global__ void __launch_bounds__(256, 2)
flash_kernel(const f16* __restrict__ qkvh, const f16* __restrict__ mbias,
             f16* __restrict__ ctx)
{
    extern __shared__ __align__(128) char smem[];
    const uint32_t sb = smem_u32(smem);
    const int tid = threadIdx.x, lane = tid & 31, w = tid >> 5;
    const int wm = w * 16;
    const int qt = blockIdx.x, bh = blockIdx.y, brn = blockIdx.z;
    const int b = bh >> 2, h = bh & 3;
    const size_t rowbase = (size_t)b * Sk;
    const f16* Qh = qkvh + (rowbase + qt * 128) * QKVN + brn * 1536 + h * DKk;
    const f16* Kh = qkvh + rowbase * QKVN + brn * 1536 + 512 + h * DKk;
    const f16* Vh = qkvh + rowbase * QKVN + brn * 1536 + 1024 + h * DKk;
    const f16* mp = mbias + ((size_t)brn * Bk + b) * Sk * Sk;

    auto loadK_body = [&](int kt, int stg2) {
        #pragma unroll
        for (int kc = 0; kc < 4; kc++)
            cpA64(sb + F3_KB + stg2 * F3_KS + kc * 5120,
                  Kh + (size_t)(kt * 64) * QKVN + kc * 32, QKVN, tid);
    };
    // V: full 64 rows (two 32-row sub-blocks) in ONE group
    auto loadV = [&](int kt, int stg2) {
        cpB_nn(sb + F3_VB + stg2 * F3_VS,
               Vh + (size_t)(kt * 64) * QKVN, QKVN, tid);
        cpB_nn(sb + F3_VB + stg2 * F3_VS + 8192,
               Vh + (size_t)(kt * 64 + 32) * QKVN, QKVN, tid);
        CP_COMMIT();
    };

    // group 0: Q (resident) + K tile 0 ; group 1: V tile 0
    #pragma unroll
    for (int c = 0; c < 4; c++)
        cpA(sb + F3_QB + c * 10240, Qh + c * 32, QKVN, tid);
    loadK_body(0, 0);
    CP_COMMIT();
    loadV(0, 0);

    float m0 = -1e30f, m1 = -1e30f, l0 = 0.f, l1 = 0.f;
    float acc_o[16][4];
    #pragma unroll
    for (int j = 0; j < 16; j++)
        #pragma unroll
        for (int q = 0; q < 4; q++) acc_o[j][q] = 0.f;

    const float scale = 0.08838834764831845f;  // 1/sqrt(128)
    const int r0loc = qt * 128 + wm + (lane >> 2);

    for (int kt = 0; kt < 8; kt++) {
        // wait K(kt): only V(kt) may remain outstanding
        CP_WAIT(1);
        __syncthreads();

        float acc_s[8][4];
        #pragma unroll
        for (int j = 0; j < 8; j++)
            #pragma unroll
            for (int q = 0; q < 4; q++) acc_s[j][q] = 0.f;

        // ---- S = Qh @ Kh^T over 4 dk-chunks (64 k-rows) ----
        #pragma unroll
        for (int kc = 0; kc < 4; kc++) {
            uint32_t QCH = sb + F3_QB + kc * 10240;
            uint32_t KC  = sb + F3_KB + (kt & 1) * F3_KS + kc * 5120;
            #pragma unroll
            for (int s = 0; s < 2; s++) {
                uint32_t ah[4];
                ldsm4(ah, QCH + (uint32_t)((wm + (lane & 15)) * 80
                          + (s * 2 + (lane >> 4)) * 16));
                uint32_t bh4[4][4];
                #pragma unroll
                for (int t = 0; t < 4; t++)
                    ldsm4(bh4[t], KC + (uint32_t)((t * 16 + (lane & 15)) * 80
                              + (s * 2 + (lane >> 4)) * 16));
                #pragma unroll
                for (int t = 0; t < 4; t++)
                    #pragma unroll
                    for (int o = 0; o < 2; o++)
                        mma_f16(acc_s[t * 2 + o], ah, bh4[t][o], bh4[t][o + 2]);
            }
        }
        // K(kt+1) writes the stage last read during kt-1's S phase; all warps
        // passed this iteration's top barrier since then => no hazard.
        if (kt < 7) { loadK_body(kt + 1, (kt + 1) & 1); CP_COMMIT(); }

        // ---- additive mask + scale + online softmax (64 cols) ----
        const f16* mrow0 = mp + (size_t)r0loc * Sk + kt * 64;
        const f16* mrow1 = mrow0 + 8 * Sk;
        float rmax0 = -1e30f, rmax1 = -1e30f;
        #pragma unroll
        for (int j = 0; j < 8; j++) {
            int col = j * 8 + (lane & 3) * 2;
            f162 q0 = *(const f162*)(mrow0 + col);
            f162 q1 = *(const f162*)(mrow1 + col);
            acc_s[j][0] = acc_s[j][0] * scale + __half2float(__low2half(q0));
            acc_s[j][1] = acc_s[j][1] * scale + __half2float(__high2half(q0));
            acc_s[j][2] = acc_s[j][2] * scale + __half2float(__low2half(q1));
            acc_s[j][3] = acc_s[j][3] * scale + __half2float(__high2half(q1));
            rmax0 = fmaxf(rmax0, fmaxf(acc_s[j][0], acc_s[j][1]));
            rmax1 = fmaxf(rmax1, fmaxf(acc_s[j][2], acc_s[j][3]));
        }
        rmax0 = fmaxf(rmax0, __shfl_xor_sync(0xffffffffu, rmax0, 1));
        rmax0 = fmaxf(rmax0, __shfl_xor_sync(0xffffffffu, rmax0, 2));
        rmax1 = fmaxf(rmax1, __shfl_xor_sync(0xffffffffu, rmax1, 1));
        rmax1 = fmaxf(rmax1, __shfl_xor_sync(0xffffffffu, rmax1, 2));
        float mn0 = fmaxf(m0, rmax0), mn1 = fmaxf(m1, rmax1);
        float f0 = __expf(m0 - mn0), f1 = __expf(m1 - mn1);
        float rs0 = 0.f, rs1 = 0.f;
        #pragma unroll
        for (int j = 0; j < 8; j++) {
            float p0 = __expf(acc_s[j][0] - mn0);
            float p1 = __expf(acc_s[j][1] - mn0);
            float p2 = __expf(acc_s[j][2] - mn1);
            float p3 = __expf(acc_s[j][3] - mn1);
            acc_s[j][0] = p0; acc_s[j][1] = p1;
            acc_s[j][2] = p2; acc_s[j][3] = p3;
            rs0 += p0 + p1; rs1 += p2 + p3;
        }
        rs0 += __shfl_xor_sync(0xffffffffu, rs0, 1);
        rs0 += __shfl_xor_sync(0xffffffffu, rs0, 2);
        rs1 += __shfl_xor_sync(0xffffffffu, rs1, 1);
        rs1 += __shfl_xor_sync(0xffffffffu, rs1, 2);
        l0 = l0 * f0 + rs0; l1 = l1 * f1 + rs1;
        m0 = mn0; m1 = mn1;
        #pragma unroll
        for (int j = 0; j < 16; j++) {
            acc_o[j][0] *= f0; acc_o[j][1] *= f0;
            acc_o[j][2] *= f1; acc_o[j][3] *= f1;
        }

        // ---- O += P @ V over the full 64-row V stage (one sync window) ----
        if (kt < 7) { CP_WAIT(1); } else { CP_WAIT(0); }   // wait V(kt)
        __syncthreads();
        uint32_t VST = sb + F3_VB + (kt & 1) * F3_VS;
        #pragma unroll
        for (int c = 0; c < 2; c++) {
            uint32_t VSUB = VST + (uint32_t)(c * 8192);
            #pragma unroll
            for (int s = 0; s < 2; s++) {
                int j0 = c * 4 + s * 2;
                uint32_t ph[4];
                ph[0] = pack_h2(acc_s[j0][0],     acc_s[j0][1]);
                ph[1] = pack_h2(acc_s[j0][2],     acc_s[j0][3]);
                ph[2] = pack_h2(acc_s[j0 + 1][0], acc_s[j0 + 1][1]);
                ph[3] = pack_h2(acc_s[j0 + 1][2], acc_s[j0 + 1][3]);
                int lk = s * 16 + (lane & 7) + ((lane >> 3) & 1) * 8;
                int cb = lane >> 4;
                uint32_t ro = VSUB + (uint32_t)(lk * 256);
                #pragma unroll
                for (int half = 0; half < 2; half++) {
                    uint32_t vh4[4][4];
                    #pragma unroll
                    for (int t = 0; t < 4; t++) {
                        int t2 = half * 4 + t;
                        uint32_t off = ro + (uint32_t)(((cb + t2 * 2) ^ (lk & 7)) << 4);
                        ldsm4t(vh4[t], off);
                    }
                    #pragma unroll
                    for (int t = 0; t < 4; t++)
                        #pragma unroll
                        for (int o = 0; o < 2; o++) {
                            int j = (half * 4 + t) * 2 + o;
                            mma_f16(acc_o[j], ph, vh4[t][o * 2], vh4[t][o * 2 + 1]);
                        }
                }
            }
        }
        __syncthreads();
        // V(kt+1) writes stage (kt+1)&1 (held V(kt-1), consumed at kt-1)
        if (kt < 7) loadV(kt + 1, (kt + 1) & 1);
    }

    // ---- epilogue: normalize + store ctx (fp16) ----
    float i0 = 1.f / l0, i1 = 1.f / l1;
    size_t gr0 = rowbase + (size_t)r0loc;
    int cc0 = brn * 512 + h * DKk;
    #pragma unroll
    for (int j = 0; j < 16; j++) {
        int col = cc0 + j * 8 + (lane & 3) * 2;
        hstore2(ctx, gr0 * 1536 + col, acc_o[j][0] * i0, acc_o[j][1] * i0);
        hstore2(ctx, (gr0 + 8) * 1536 + col, acc_o[j][2] * i1, acc_o[j][3] * i1);
    }
}

// ==================== weight prep (launch #1) ================================
__global__ void prep_w_kernel(const float* __restrict__ aw,
                              const float* __restrict__ ab,
                              const float* __restrict__ ff_w1,
                              const float* __restrict__ ff_w2,
                              const float* __restrict__ out1_w,
                              const float* __restrict__ out2_w,
                              f16* __restrict__ qkvwh, f16* __restrict__ wouth,
                              float* __restrict__ qkvb, float* __restrict__ woutb,
                              f16* __restrict__ f1h, f16* __restrict__ f2h,
                              f16* __restrict__ o1wh, f16* __restrict__ o2wh)
{
    int blk = blockIdx.x;
    if (blk < 18432) {
        size_t o = ((size_t)blk * 256 + threadIdx.x) * 2;
        size_t per = (size_t)Dk * QKVN;
        int l = (int)(o / per);
        size_t r = o % per;
        int k = (int)(r / QKVN);
        int c = (int)(r % QKVN);
        int brn = c / 1536, rem = c % 1536;
        int j = rem >> 9, n = rem & 511;
        const float* src = aw + ((((size_t)(l * 3 + brn) * 4 + j) * Dk + k) * Dk + n);
        float2 v = *(const float2*)src;
        hstore2(qkvwh, o, v.x, v.y);
    } else if (blk < 24576) {
        size_t o = ((size_t)(blk - 18432) * 256 + threadIdx.x) * 2;
        size_t per = (size_t)1536 * Dk;
        int l = (int)(o / per);
        size_t r = o % per;
        int k = (int)(r / Dk);
        int n = (int)(r % Dk);
        int brn = k / 512, kk = k % 512;
        const float* src = aw + ((((size_t)(l * 3 + brn) * 4 + 3) * Dk + kk) * Dk + n);
        float2 v = *(const float2*)src;
        hstore2(wouth, o, v.x, v.y);
    } else if (blk < 26624) {
        int i = ((blk - 24576) * 256 + threadIdx.x) * 4;
        float4 v = *(const float4*)(ff_w1 + i);
        hstore2(f1h, i, v.x, v.y);
        hstore2(f1h, i + 2, v.z, v.w);
    } else if (blk < 28672) {
        int i = ((blk - 26624) * 256 + threadIdx.x) * 4;
        float4 v = *(const float4*)(ff_w2 + i);
        hstore2(f2h, i, v.x, v.y);
        hstore2(f2h, i + 2, v.z, v.w);
    } else if (blk < 28928) {
        int i = ((blk - 28672) * 256 + threadIdx.x) * 4;
        float4 v = *(const float4*)(out1_w + i);
        hstore2(o1wh, i, v.x, v.y);
        hstore2(o1wh, i + 2, v.z, v.w);
    } else if (blk < 29056) {
        int i = ((blk - 28928) * 256 + threadIdx.x) * 4;
        float4 v = *(const float4*)(out2_w + i);
        hstore2(o2wh, i, v.x, v.y);
        hstore2(o2wh, i + 2, v.z, v.w);
    } else if (blk < 29128) {
        int o = (blk - 29056) * 256 + threadIdx.x;
        int l = o / QKVN, c = o % QKVN;
        int brn = c / 1536, rem = c % 1536;
        int j = rem >> 9, n = rem & 511;
        qkvb[o] = ab[((l * 3 + brn) * 4 + j) * Dk + n];
    } else {
        int o = (blk - 29128) * 256 + threadIdx.x;
        int l = o / Dk, n = o % Dk;
        float s = 0.f;
        for (int brn = 0; brn < 3; brn++)
            s += ab[((l * 3 + brn) * 4 + 3) * Dk + n];
        woutb[o] = s;
    }
}

// ==================== mask prep (launch #2) ==================================
__global__ void prep_mask_kernel(const int* __restrict__ dmask,
                                 const int* __restrict__ smask,
                                 const int* __restrict__ gmask,
                                 f16* __restrict__ mbias)
{
    size_t o = ((size_t)blockIdx.x * 256 + threadIdx.x) * 4;
    const size_t per = (size_t)Bk * Sk * Sk;
    int brn = (int)(o / per);
    size_t r = o % per;
    const int* src = (brn == 0) ? dmask : (brn == 1) ? smask : gmask;
    int4 m = *(const int4*)(src + r);
    f16* dst = mbias + o;
    dst[0] = __float2half_rn(m.x ? -1e4f : 0.f);
    dst[1] = __float2half_rn(m.y ? -1e4f : 0.f);
    dst[2] = __float2half_rn(m.z ? -1e4f : 0.f);
    dst[3] = __float2half_rn(m.w ? -1e4f : 0.f);
}

// ==================== reductions ============================================
__device__ __forceinline__ float warpReduceSum(float v) {
    #pragma unroll
    for (int o = 16; o > 0; o >>= 1) v += __shfl_xor_sync(0xffffffffu, v, o);
    return v;
}

// ==================== fused input projection + inorm (layer 0) ==============
__global__ void input_proj_inorm_kernel(const float* __restrict__ x,
                                        const float* __restrict__ cond,
                                        const float* __restrict__ in_w,
                                        const float* __restrict__ in_b,
                                        const float* __restrict__ cond_w,
                                        const float* __restrict__ cond_b,
                                        float* __restrict__ h,
                                        f16* __restrict__ y)
{
    __shared__ float xs[2][18];
    __shared__ float cs[2][89];
    __shared__ float s1[8], s2[8];
    int tok0 = blockIdx.x * 2;
    int t = threadIdx.x;          // 256
    if (t < 36)  xs[t / 18][t % 18] = x[(size_t)tok0 * 18 + t];
    if (t < 178) cs[t / 89][t % 89] = cond[(size_t)tok0 * 89 + t];
    __syncthreads();
    int half = t >> 7, lt = t & 127;
    int col = lt * 4;
    float4 ib = *(const float4*)(in_b + col);
    float4 cbv = *(const float4*)(cond_b + col);
    float a0 = ib.x + cbv.x, a1 = ib.y + cbv.y, a2 = ib.z + cbv.z, a3 = ib.w + cbv.w;
    #pragma unroll 3
    for (int k = 0; k < 18; k++) {
        float4 wv = *(const float4*)(in_w + k * Dk + col);
        float xv = xs[half][k];
        a0 = fmaf(xv, wv.x, a0); a1 = fmaf(xv, wv.y, a1);
        a2 = fmaf(xv, wv.z, a2); a3 = fmaf(xv, wv.w, a3);
    }
    #pragma unroll 3
    for (int k = 0; k < 89; k++) {
        float4 wv = *(const float4*)(cond_w + k * Dk + col);
        float cv = cs[half][k];
        a0 = fmaf(cv, wv.x, a0); a1 = fmaf(cv, wv.y, a1);
        a2 = fmaf(cv, wv.z, a2); a3 = fmaf(cv, wv.w, a3);
    }
    const size_t base = (size_t)(tok0 + half) * Dk;
    float4 r; r.x = a0; r.y = a1; r.z = a2; r.w = a3;
    *(float4*)(h + base + col) = r;
    float sum = warpReduceSum(a0 + a1 + a2 + a3);
    float sq  = warpReduceSum(a0*a0 + a1*a1 + a2*a2 + a3*a3);
    int wid = t >> 5;
    if ((t & 31) == 0) { s1[wid] = sum; s2[wid] = sq; }
    __syncthreads();
    int h4 = half * 4;
    float tot = s1[h4] + s1[h4+1] + s1[h4+2] + s1[h4+3];
    float tsq = s2[h4] + s2[h4+1] + s2[h4+2] + s2[h4+3];
    float mean = tot * (1.f / Dk);
    float var  = tsq * (1.f / Dk) - mean * mean;
    float rr = rsqrtf(var + 1e-5f);
    hstore2(y, base + col,     (a0 - mean) * rr, (a1 - mean) * rr);
    hstore2(y, base + col + 2, (a2 - mean) * rr, (a3 - mean) * rr);
}

// ==================== instance norm =========================================
__global__ void inorm_kernel(const float* __restrict__ x, f16* __restrict__ y)
{
    __shared__ float s1[8], s2[8];
    const size_t base = (size_t)blockIdx.x * Dk;
    int t = threadIdx.x;          // 256
    float a = x[base + t], b = x[base + t + 256];
    float sum = warpReduceSum(a + b);
    float sq  = warpReduceSum(a * a + b * b);
    if ((t & 31) == 0) { s1[t >> 5] = sum; s2[t >> 5] = sq; }
    __syncthreads();
    if (t < 32) {
        float v1 = (t < 8) ? s1[t] : 0.f;
        float v2 = (t < 8) ? s2[t] : 0.f;
        v1 = warpReduceSum(v1);
        v2 = warpReduceSum(v2);
        if (t == 0) { s1[0] = v1; s2[0] = v2; }
    }
    __syncthreads();
    float mean = s1[0] * (1.f / Dk);
    float var  = s2[0] * (1.f / Dk) - mean * mean;
    float r = rsqrtf(var + 1e-5f);
    y[base + t]       = __float2half_rn((a - mean) * r);
    y[base + t + 256] = __float2half_rn((b - mean) * r);
}

// ==================== split (for output head) ================================
__global__ void split_kernel(const float* __restrict__ x, f16* __restrict__ y)
{
    int i = (blockIdx.x * 256 + threadIdx.x) * 4;
    float4 v = *(const float4*)(x + i);
    hstore2(y, i,     v.x, v.y);
    hstore2(y, i + 2, v.z, v.w);
}

// ==================== final tiny head =======================================
__global__ void out3_kernel(const float* __restrict__ o2,
                            const float* __restrict__ w,
                            const float* __restrict__ b,
                            float* __restrict__ out)
{
    int idx = blockIdx.x * 256 + threadIdx.x;
    if (idx >= Bk * Sk * 2) return;
    int tok = idx >> 1, j = idx & 1;
    const float* o = o2 + (size_t)tok * 256;
    float acc = b[j];
    #pragma unroll 8
    for (int kk = 0; kk < 256; kk++) acc = fmaf(o[kk], w[kk * 2 + j], acc);
    out[idx] = acc;
}

// ============================ host launcher =================================
extern "C" void kernel_launch(void* const* d_in, const int* in_sizes, int n_in,
                              void* d_out, int out_size)
{
    const float* x      = (const float*)d_in[0];
    const float* cond   = (const float*)d_in[1];
    const int*   dmask  = (const int*)  d_in[2];
    const int*   smask  = (const int*)  d_in[3];
    const int*   gmask  = (const int*)  d_in[4];
    const float* attn_w = (const float*)d_in[5];
    const float* attn_b = (const float*)d_in[6];
    const float* ff_w1  = (const float*)d_in[7];
    const float* ff_b1  = (const float*)d_in[8];
    const float* ff_w2  = (const float*)d_in[9];
    const float* ff_b2  = (const float*)d_in[10];
    const float* in_w   = (const float*)d_in[11];
    const float* in_b   = (const float*)d_in[12];
    const float* cond_w = (const float*)d_in[13];
    const float* cond_b = (const float*)d_in[14];
    const float* out1_w = (const float*)d_in[15];
    const float* out1_b = (const float*)d_in[16];
    const float* out2_w = (const float*)d_in[17];
    const float* out2_b = (const float*)d_in[18];
    const float* out3_w = (const float*)d_in[19];
    const float* out3_b = (const float*)d_in[20];

    float *h, *o2, *qkvb, *woutb;
    f16 *h2, *qkvh, *ctx, *f, *mbias;
    f16 *qkvwh, *wouth, *f1h, *f2h, *o1wh, *o2wh;
    cudaGetSymbolAddress((void**)&h,      g_h);
    cudaGetSymbolAddress((void**)&o2,     g_o2);
    cudaGetSymbolAddress((void**)&qkvb,   g_qkvb);
    cudaGetSymbolAddress((void**)&woutb,  g_woutb);
    cudaGetSymbolAddress((void**)&h2,     g_h2);
    cudaGetSymbolAddress((void**)&qkvh,   g_qkvh);
    cudaGetSymbolAddress((void**)&ctx,    g_ctx);
    cudaGetSymbolAddress((void**)&f,      g_f);
    cudaGetSymbolAddress((void**)&mbias,  g_mbias);
    cudaGetSymbolAddress((void**)&qkvwh,  g_qkvwh);
    cudaGetSymbolAddress((void**)&wouth,  g_wouth);
    cudaGetSymbolAddress((void**)&f1h,    g_f1h);
    cudaGetSymbolAddress((void**)&f2h,    g_f2h);
    cudaGetSymbolAddress((void**)&o1wh,   g_o1wh);
    cudaGetSymbolAddress((void**)&o2wh,   g_o2wh);

    cudaFuncSetAttribute(wgemm_kernel<false,false,true>,
                         cudaFuncAttributeMaxDynamicSharedMemorySize, SM_NN3);
    cudaFuncSetAttribute(wgemm_kernel<true,false,true>,
                         cudaFuncAttributeMaxDynamicSharedMemorySize, SM_NN3);
    cudaFuncSetAttribute(wgemm_kernel<false,true,false>,
                         cudaFuncAttributeMaxDynamicSharedMemorySize, SM_NN3);
    cudaFuncSetAttribute(wgemm_kernel<true,false,false>,
                         cudaFuncAttributeMaxDynamicSharedMemorySize, SM_NN3);
    cudaFuncSetAttribute(flash_kernel,
                         cudaFuncAttributeMaxDynamicSharedMemorySize, F3_SM);

    const int M = Bk * Sk;           // 8192

    // #1: weight prep
    prep_w_kernel<<<29136, 256>>>(attn_w, attn_b, ff_w1, ff_w2, out1_w, out2_w,
                                  qkvwh, wouth, qkvb, woutb, f1h, f2h, o1wh, o2wh);
    // #2: mask prep
    prep_mask_kernel<<<12288, 256>>>(dmask, smask, gmask, mbias);

    // #3: input projection + layer-0 inorm fused
    input_proj_inorm_kernel<<<M / 2, 256>>>(x, cond, in_w, in_b, cond_w, cond_b,
                                            h, h2);

    for (int l = 0; l < Lk; l++) {
        if (l > 0) inorm_kernel<<<M, 256>>>(h, h2);
        // #4 (l=0): fused qkv (R15 winner config)
        wgemm_kernel<false,false,true><<<dim3(QKVN/128, 64), 128, SM_NN3>>>(
            h2, qkvwh + (size_t)l * Dk * QKVN, qkvb + (size_t)l * QKVN,
            nullptr, qkvh, M, QKVN, Dk);
        flash_kernel<<<dim3(4, Bk*Hh, 3), 256, F3_SM>>>(qkvh, mbias, ctx);
        wgemm_kernel<false,true,false><<<dim3(4, 64), 128, SM_NN3>>>(
            ctx, wouth + (size_t)l * 1536 * Dk, woutb + (size_t)l * Dk,
            h, nullptr, M, Dk, 1536);
        inorm_kernel<<<M, 256>>>(h, h2);
        wgemm_kernel<true,false,true><<<dim3(8, 64), 128, SM_NN3>>>(
            h2, f1h + (size_t)l*Dk*FFk, ff_b1 + (size_t)l*FFk,
            nullptr, f, M, FFk, Dk);
        wgemm_kernel<false,true,false><<<dim3(4, 64), 128, SM_NN3>>>(
            f, f2h + (size_t)l*FFk*Dk, ff_b2 + (size_t)l*Dk,
            h, nullptr, M, Dk, FFk);
    }

    // output head
    split_kernel<<<(M * Dk) / 1024, 256>>>(h, h2);
    wgemm_kernel<true,false,true><<<dim3(4, 64), 128, SM_NN3>>>(
        h2, o1wh, out1_b, nullptr, ctx, M, Dk, Dk);
    wgemm_kernel<true,false,false><<<dim3(2, 64), 128, SM_NN3>>>(
        ctx, o2wh, out2_b, o2, nullptr, M, Dk/2, Dk);
    out3_kernel<<<(M * 2 + 255) / 256, 256>>>(o2, out3_w, out3_b, (float*)d_out);
}